// round 1
// baseline (speedup 1.0000x reference)
#include <cuda_runtime.h>
#include <math.h>
#include <float.h>

// Problem constants (fixed by the dataset)
#define S_   7
#define B_   2
#define C_   80
#define NGT  32
#define BT_  8192
#define CELLF 90            // B*5 + C
#define NCELLS (BT_ * S_ * S_)      // 401408
#define NBOX   (NCELLS * B_)        // 802816
#define NGTS   (BT_ * NGT)          // 262144

#define NBLK 1184           // 148 SMs * 8
#define NTHR 256
#define NWARP (NTHR / 32)

// Per-block partial sums: [coord, obj, posconf_sq, cls, npos, noobj_all]
__device__ double g_part[NBLK][6];

__device__ __forceinline__ float sigmoidf_(float x) {
    return 1.0f / (1.0f + __expf(-x));
}

__global__ void __launch_bounds__(NTHR)
yolo_loss_main(const float* __restrict__ preds,
               const float* __restrict__ gt_boxes,
               const int* __restrict__ gt_labels,
               const unsigned char* __restrict__ gt_valid)
{
    const int tid  = threadIdx.x;
    const int lane = tid & 31;
    const int wid  = tid >> 5;
    const unsigned FULL = 0xffffffffu;

    float coord = 0.f, obj = 0.f, posconf = 0.f, clsl = 0.f, npos = 0.f, noobj = 0.f;

    // ---------------- Phase 1: one warp per GT ----------------
    const int gwarp  = blockIdx.x * NWARP + wid;
    const int nwarps = gridDim.x * NWARP;

    for (int gt = gwarp; gt < NGTS; gt += nwarps) {
        const bool valid = (gt_valid[gt] != 0);   // warp-uniform
        if (!valid) continue;

        const float4 gb = __ldg(((const float4*)gt_boxes) + gt);
        const int label = __ldg(gt_labels + gt);
        const float x1 = gb.x, y1 = gb.y, x2 = gb.z, y2 = gb.w;
        const float cx = (x1 + x2) * 0.5f;
        const float cy = (y1 + y2) * 0.5f;
        const float w  = fmaxf(x2 - x1, 1e-6f);
        const float h  = fmaxf(y2 - y1, 1e-6f);
        const int gi = min(max((int)floorf(cx * (float)S_), 0), S_ - 1);
        const int gj = min(max((int)floorf(cy * (float)S_), 0), S_ - 1);

        const int b = gt >> 5;  // gt / NGT
        const float* __restrict__ cell =
            preds + (size_t)(b * (S_ * S_) + gj * S_ + gi) * CELLF;

        // ---- class softmax: 80 logits, lanes cover [lane, lane+32, lane+64] ----
        const float v0 = __ldg(cell + 10 + lane);
        const float v1 = __ldg(cell + 42 + lane);
        const float v2 = (lane < 16) ? __ldg(cell + 74 + lane) : -FLT_MAX;

        float m = fmaxf(fmaxf(v0, v1), v2);
        #pragma unroll
        for (int o = 16; o; o >>= 1) m = fmaxf(m, __shfl_xor_sync(FULL, m, o));

        const float e0 = __expf(v0 - m);
        const float e1 = __expf(v1 - m);
        const float e2 = (lane < 16) ? __expf(v2 - m) : 0.f;

        float s  = e0 + e1 + e2;
        float sq = e0 * e0 + e1 * e1 + e2 * e2;
        float el = 0.f;
        if (label < 32)      { if (lane == label)      el = e0; }
        else if (label < 64) { if (lane == label - 32) el = e1; }
        else                 { if (lane == label - 64) el = e2; }

        #pragma unroll
        for (int o = 16; o; o >>= 1) {
            s  += __shfl_xor_sync(FULL, s,  o);
            sq += __shfl_xor_sync(FULL, sq, o);
            el += __shfl_xor_sync(FULL, el, o);
        }
        const float inv = 1.0f / s;
        const float cls_term = sq * inv * inv - 2.0f * el * inv + 1.0f;

        // ---- box part: lanes 0..9 fetch the 10 box floats, broadcast ----
        const float bx = (lane < 10) ? __ldg(cell + lane) : 0.f;
        float t[10];
        #pragma unroll
        for (int i = 0; i < 10; i++) t[i] = __shfl_sync(FULL, bx, i);

        const float area_g = (x2 - x1) * (y2 - y1);
        float iou[2];
        #pragma unroll
        for (int k = 0; k < 2; k++) {
            const float tx = t[k*5+0], ty = t[k*5+1], tw = t[k*5+2], th = t[k*5+3];
            const float px = (sigmoidf_(tx) + (float)gi) * (1.0f / S_);
            const float py = (sigmoidf_(ty) + (float)gj) * (1.0f / S_);
            const float pw = tw * tw, ph = th * th;
            const float px1 = px - 0.5f * pw, px2v = px + 0.5f * pw;
            const float py1 = py - 0.5f * ph, py2v = py + 0.5f * ph;
            const float iw = fmaxf(0.f, fminf(px2v, x2) - fmaxf(px1, x1));
            const float ih = fmaxf(0.f, fminf(py2v, y2) - fmaxf(py1, y1));
            const float inter = iw * ih;
            iou[k] = inter / (pw * ph + area_g - inter + 1e-6f);
        }
        const int   best = (iou[1] > iou[0]) ? 1 : 0;
        const float iou_best = fmaxf(iou[0], iou[1]);

        if (lane == 0) {
            const float tx = t[best*5+0], ty = t[best*5+1];
            const float tw = t[best*5+2], th = t[best*5+3], to = t[best*5+4];
            const float sx = sigmoidf_(tx), sy = sigmoidf_(ty), so = sigmoidf_(to);
            const float tgx = cx * (float)S_ - (float)gi;
            const float tgy = cy * (float)S_ - (float)gj;
            const float tgw = sqrtf(w), tgh = sqrtf(h);
            const float dx = sx - tgx, dy = sy - tgy, dw = tw - tgw, dh = th - tgh;
            coord   += dx*dx + dy*dy + dw*dw + dh*dh;
            const float dob = so - iou_best;
            obj     += dob * dob;
            posconf += so * so;
            npos    += 1.0f;
            clsl    += cls_term;   // reduction result valid on all lanes
        }
    }

    // ---------------- Phase 2: conf over ALL boxes ----------------
    const int gthread = blockIdx.x * NTHR + tid;
    const int nth     = NBLK * NTHR;
    for (int i = gthread; i < NBOX; i += nth) {
        const int cellg = i >> 1;
        const int k     = i & 1;
        const float to  = __ldg(preds + (size_t)cellg * CELLF + 4 + k * 5);
        const float so  = sigmoidf_(to);
        noobj += so * so;
    }

    // ---------------- Block reduction -> g_part ----------------
    float vals[6] = {coord, obj, posconf, clsl, npos, noobj};
    #pragma unroll
    for (int j = 0; j < 6; j++) {
        #pragma unroll
        for (int o = 16; o; o >>= 1)
            vals[j] += __shfl_xor_sync(FULL, vals[j], o);
    }
    __shared__ double sh[NWARP][6];
    if (lane == 0) {
        #pragma unroll
        for (int j = 0; j < 6; j++) sh[wid][j] = (double)vals[j];
    }
    __syncthreads();
    if (tid < 6) {
        double acc = 0.0;
        #pragma unroll
        for (int wI = 0; wI < NWARP; wI++) acc += sh[wI][tid];
        g_part[blockIdx.x][tid] = acc;
    }
}

__global__ void __launch_bounds__(256)
yolo_loss_finalize(float* __restrict__ out)
{
    const unsigned FULL = 0xffffffffu;
    double a[6] = {0, 0, 0, 0, 0, 0};
    for (int b = threadIdx.x; b < NBLK; b += blockDim.x) {
        #pragma unroll
        for (int j = 0; j < 6; j++) a[j] += g_part[b][j];
    }
    #pragma unroll
    for (int j = 0; j < 6; j++) {
        #pragma unroll
        for (int o = 16; o; o >>= 1)
            a[j] += __shfl_xor_sync(FULL, a[j], o);
    }
    __shared__ double sh[8][6];
    const int wid = threadIdx.x >> 5, lane = threadIdx.x & 31;
    if (lane == 0) {
        #pragma unroll
        for (int j = 0; j < 6; j++) sh[wid][j] = a[j];
    }
    __syncthreads();
    if (threadIdx.x == 0) {
        double t[6];
        #pragma unroll
        for (int j = 0; j < 6; j++) {
            t[j] = 0.0;
            for (int wI = 0; wI < 8; wI++) t[j] += sh[wI][j];
        }
        const double npos  = fmax(t[4], 1.0);
        const double nneg  = fmax((double)NBOX - t[4], 1.0);
        const double ncell = fmax(t[4], 1.0);   // GT cells are distinct per batch item
        const double loss = 5.0 * t[0] / npos        // LC * coord
                          + t[1] / npos              // obj
                          + 0.5 * (t[5] - t[2]) / nneg  // LN * noobj (all - positive)
                          + t[3] / ncell;            // cls
        *out = (float)loss;
    }
}

extern "C" void kernel_launch(void* const* d_in, const int* in_sizes, int n_in,
                              void* d_out, int out_size)
{
    const float*         preds     = (const float*)d_in[0];
    const float*         gt_boxes  = (const float*)d_in[1];
    const int*           gt_labels = (const int*)d_in[2];
    const unsigned char* gt_valid  = (const unsigned char*)d_in[3];
    float* out = (float*)d_out;

    yolo_loss_main<<<NBLK, NTHR>>>(preds, gt_boxes, gt_labels, gt_valid);
    yolo_loss_finalize<<<1, 256>>>(out);
}

// round 2
// speedup vs baseline: 1.1547x; 1.1547x over previous
#include <cuda_runtime.h>
#include <math.h>
#include <float.h>

// Problem constants (fixed by the dataset)
#define S_   7
#define B_   2
#define C_   80
#define NGT  32
#define BT_  8192
#define CELLF 90                    // B*5 + C
#define NCELLS (BT_ * S_ * S_)      // 401408
#define NBOX   (NCELLS * B_)        // 802816
#define NGTS   (BT_ * NGT)          // 262144

#define NBLK 1184                   // 148 SMs * 8
#define NTHR 256
#define NWARP (NTHR / 32)

// Per-block partial sums: [coord, obj, posconf_sq, cls, npos, noobj_all]
__device__ double g_part[NBLK][6];
__device__ unsigned int g_count = 0;

__device__ __forceinline__ float sigmoidf_(float x) {
    return 1.0f / (1.0f + __expf(-x));
}

__global__ void __launch_bounds__(NTHR)
yolo_loss_fused(const float* __restrict__ preds,
                const float* __restrict__ gt_boxes,
                const int* __restrict__ gt_labels,
                const unsigned char* __restrict__ gt_valid,
                float* __restrict__ out)
{
    const int tid  = threadIdx.x;
    const int lane = tid & 31;
    const int wid  = tid >> 5;
    const unsigned FULL = 0xffffffffu;

    float coord = 0.f, obj = 0.f, posconf = 0.f, clsl = 0.f, npos = 0.f, noobj = 0.f;

    // ---------------- Phase 1: one warp per GT ----------------
    const int gwarp  = blockIdx.x * NWARP + wid;
    const int nwarps = NBLK * NWARP;

    #pragma unroll 2
    for (int gt = gwarp; gt < NGTS; gt += nwarps) {
        const bool valid = (__ldg(gt_valid + gt) != 0);   // warp-uniform
        if (!valid) continue;

        const float4 gb = __ldg(((const float4*)gt_boxes) + gt);
        const int label = __ldg(gt_labels + gt);
        const float x1 = gb.x, y1 = gb.y, x2 = gb.z, y2 = gb.w;
        const float cx = (x1 + x2) * 0.5f;
        const float cy = (y1 + y2) * 0.5f;
        const float w  = fmaxf(x2 - x1, 1e-6f);
        const float h  = fmaxf(y2 - y1, 1e-6f);
        const int gi = min(max((int)floorf(cx * (float)S_), 0), S_ - 1);
        const int gj = min(max((int)floorf(cy * (float)S_), 0), S_ - 1);

        const int b = gt >> 5;  // gt / NGT
        const float* __restrict__ cell =
            preds + (size_t)(b * (S_ * S_) + gj * S_ + gi) * CELLF;

        // ---- lane 0: issue the 10 box-float loads early (overlap latency) ----
        float2 c01, c23, c45, c67, c89;
        if (lane == 0) {
            const float2* cp = (const float2*)cell;   // 360B stride -> 8B aligned
            c01 = __ldg(cp + 0); c23 = __ldg(cp + 1);
            c45 = __ldg(cp + 2); c67 = __ldg(cp + 3);
            c89 = __ldg(cp + 4);
        }

        // ---- class softmax (no max-subtraction; logits are small) ----
        const float v0 = __ldg(cell + 10 + lane);
        const float v1 = __ldg(cell + 42 + lane);
        const float e0 = __expf(v0);
        const float e1 = __expf(v1);
        float e2 = 0.f;
        if (lane < 16) e2 = __expf(__ldg(cell + 74 + lane));

        float s  = e0 + e1 + e2;
        float sq = e0 * e0 + e1 * e1 + e2 * e2;
        // exp at the label position: single indexed shuffle instead of a tree
        const float ev = (label < 32) ? e0 : ((label < 64) ? e1 : e2);
        const float el = __shfl_sync(FULL, ev, label & 31);

        #pragma unroll
        for (int o = 16; o; o >>= 1) {
            s  += __shfl_xor_sync(FULL, s,  o);
            sq += __shfl_xor_sync(FULL, sq, o);
        }

        if (lane == 0) {
            const float inv = 1.0f / s;
            clsl += sq * inv * inv - 2.0f * el * inv + 1.0f;

            // both candidate boxes, IoU, best selection — all scalar on lane 0
            const float t0[5] = {c01.x, c01.y, c23.x, c23.y, c45.x};
            const float t1[5] = {c45.y, c67.x, c67.y, c89.x, c89.y};
            const float area_g = (x2 - x1) * (y2 - y1);

            float iou[2]; float sxk[2], syk[2], twk[2], thk[2], tok[2];
            #pragma unroll
            for (int k = 0; k < 2; k++) {
                const float* t = k ? t1 : t0;
                const float sx = sigmoidf_(t[0]);
                const float sy = sigmoidf_(t[1]);
                const float pw = t[2] * t[2], ph = t[3] * t[3];
                const float px = (sx + (float)gi) * (1.0f / S_);
                const float py = (sy + (float)gj) * (1.0f / S_);
                const float px1 = px - 0.5f * pw, px2v = px + 0.5f * pw;
                const float py1 = py - 0.5f * ph, py2v = py + 0.5f * ph;
                const float iw = fmaxf(0.f, fminf(px2v, x2) - fmaxf(px1, x1));
                const float ih = fmaxf(0.f, fminf(py2v, y2) - fmaxf(py1, y1));
                const float inter = iw * ih;
                iou[k] = inter / (pw * ph + area_g - inter + 1e-6f);
                sxk[k] = sx; syk[k] = sy; twk[k] = t[2]; thk[k] = t[3]; tok[k] = t[4];
            }
            const int   best = (iou[1] > iou[0]) ? 1 : 0;
            const float iou_best = fmaxf(iou[0], iou[1]);

            const float so  = sigmoidf_(tok[best]);
            const float tgx = cx * (float)S_ - (float)gi;
            const float tgy = cy * (float)S_ - (float)gj;
            const float tgw = sqrtf(w), tgh = sqrtf(h);
            const float dx = sxk[best] - tgx, dy = syk[best] - tgy;
            const float dw = twk[best] - tgw, dh = thk[best] - tgh;
            coord   += dx*dx + dy*dy + dw*dw + dh*dh;
            const float dob = so - iou_best;
            obj     += dob * dob;
            posconf += so * so;
            npos    += 1.0f;
        }
    }

    // ---------------- Phase 2: conf over ALL cells (thread-per-cell) ----------------
    const int gthread = blockIdx.x * NTHR + tid;
    const int nth     = NBLK * NTHR;
    for (int c = gthread; c < NCELLS; c += nth) {
        const float* base = preds + (size_t)c * CELLF;
        const float so0 = sigmoidf_(__ldg(base + 4));
        const float so1 = sigmoidf_(__ldg(base + 9));
        noobj += so0 * so0 + so1 * so1;
    }

    // ---------------- Block reduction -> g_part ----------------
    float vals[6] = {coord, obj, posconf, clsl, npos, noobj};
    #pragma unroll
    for (int j = 0; j < 6; j++) {
        #pragma unroll
        for (int o = 16; o; o >>= 1)
            vals[j] += __shfl_xor_sync(FULL, vals[j], o);
    }
    __shared__ double sh[NWARP][6];
    if (lane == 0) {
        #pragma unroll
        for (int j = 0; j < 6; j++) sh[wid][j] = (double)vals[j];
    }
    __syncthreads();
    if (tid < 6) {
        double acc = 0.0;
        #pragma unroll
        for (int wI = 0; wI < NWARP; wI++) acc += sh[wI][tid];
        g_part[blockIdx.x][tid] = acc;
    }

    // ---------------- Grid-wide finalize: last block reduces ----------------
    __shared__ bool is_last;
    __threadfence();
    if (tid == 0) {
        const unsigned prev = atomicAdd(&g_count, 1u);
        is_last = (prev == (unsigned)(NBLK - 1));
        if (is_last) g_count = 0u;          // reset for the next graph replay
    }
    __syncthreads();
    if (!is_last) return;

    double a[6] = {0, 0, 0, 0, 0, 0};
    for (int bb = tid; bb < NBLK; bb += NTHR) {
        #pragma unroll
        for (int j = 0; j < 6; j++) a[j] += __ldcg(&g_part[bb][j]);
    }
    #pragma unroll
    for (int j = 0; j < 6; j++) {
        #pragma unroll
        for (int o = 16; o; o >>= 1)
            a[j] += __shfl_xor_sync(FULL, a[j], o);
    }
    __shared__ double shf[NWARP][6];
    if (lane == 0) {
        #pragma unroll
        for (int j = 0; j < 6; j++) shf[wid][j] = a[j];
    }
    __syncthreads();
    if (tid == 0) {
        double t[6];
        #pragma unroll
        for (int j = 0; j < 6; j++) {
            t[j] = 0.0;
            for (int wI = 0; wI < NWARP; wI++) t[j] += shf[wI][j];
        }
        const double nposd = fmax(t[4], 1.0);
        const double nneg  = fmax((double)NBOX - t[4], 1.0);
        const double ncell = fmax(t[4], 1.0);   // GT cells are distinct per batch item
        const double loss = 5.0 * t[0] / nposd          // LC * coord
                          + t[1] / nposd                // obj
                          + 0.5 * (t[5] - t[2]) / nneg  // LN * noobj (all - positive)
                          + t[3] / ncell;               // cls
        *out = (float)loss;
    }
}

extern "C" void kernel_launch(void* const* d_in, const int* in_sizes, int n_in,
                              void* d_out, int out_size)
{
    const float*         preds     = (const float*)d_in[0];
    const float*         gt_boxes  = (const float*)d_in[1];
    const int*           gt_labels = (const int*)d_in[2];
    const unsigned char* gt_valid  = (const unsigned char*)d_in[3];
    float* out = (float*)d_out;

    yolo_loss_fused<<<NBLK, NTHR>>>(preds, gt_boxes, gt_labels, gt_valid, out);
}

// round 3
// speedup vs baseline: 2.2368x; 1.9371x over previous
#include <cuda_runtime.h>
#include <math.h>
#include <float.h>

// Problem constants (fixed by the dataset)
#define S_   7
#define B_   2
#define C_   80
#define NGT  32
#define BT_  8192
#define CELLF 90                    // B*5 + C
#define NCELLS (BT_ * S_ * S_)      // 401408
#define NBOX   (NCELLS * B_)        // 802816
#define NGTS   (BT_ * NGT)          // 262144

#define NTHR 256
#define NBLK (NGTS / NTHR)          // 1024 blocks -> exactly 1 thread per GT
#define NWARP (NTHR / 32)

// Per-block partial sums: [coord, obj, posconf_sq, cls, npos, noobj_all]
__device__ double g_part[NBLK][6];
__device__ unsigned int g_count = 0;

__device__ __forceinline__ float sigmoidf_(float x) {
    return 1.0f / (1.0f + __expf(-x));
}

__global__ void __launch_bounds__(NTHR)
yolo_loss_fused(const float* __restrict__ preds,
                const float* __restrict__ gt_boxes,
                const int* __restrict__ gt_labels,
                const unsigned char* __restrict__ gt_valid,
                float* __restrict__ out)
{
    const int tid  = threadIdx.x;
    const int lane = tid & 31;
    const int wid  = tid >> 5;
    const int t    = blockIdx.x * NTHR + tid;      // GT index, 0..NGTS-1 exactly
    const unsigned FULL = 0xffffffffu;

    float coord = 0.f, obj = 0.f, posconf = 0.f, clsl = 0.f, npos = 0.f, noobj = 0.f;

    // ================= Phase 1: one THREAD per GT =================
    {
        const float mval = (__ldg(gt_valid + t) != 0) ? 1.0f : 0.0f;
        const float4 gb  = __ldg((const float4*)gt_boxes + t);
        const int   label = __ldg(gt_labels + t);

        const float x1 = gb.x, y1 = gb.y, x2 = gb.z, y2 = gb.w;
        const float cx = (x1 + x2) * 0.5f;
        const float cy = (y1 + y2) * 0.5f;
        const float w  = fmaxf(x2 - x1, 1e-6f);
        const float h  = fmaxf(y2 - y1, 1e-6f);
        const int gi = min(max((int)floorf(cx * (float)S_), 0), S_ - 1);
        const int gj = min(max((int)floorf(cy * (float)S_), 0), S_ - 1);

        const int  b       = t >> 5;                       // t / NGT
        const int  cellIdx = b * (S_ * S_) + gj * S_ + gi;
        const float* cell  = preds + (size_t)cellIdx * CELLF;

        // label-logit gather (independent scalar load, overlaps everything)
        const float cl = __ldg(cell + 10 + label);

        // 16B-aligned vec4 view: off = 0 (even cell) or 2 floats (odd cell)
        const int   off  = (cellIdx & 1) << 1;             // 0 or 2
        const float msh  = (float)(off >> 1);              // 1.0 if shifted
        const float mns  = 1.0f - msh;                     // 1.0 if not shifted
        const float4* v4 = (const float4*)(cell - off);

        // ---- head: loaded positions 0..11 (covers box floats + off=0 class bdry) ----
        float p[12];
        {
            const float4 a = __ldg(v4 + 0);
            const float4 bq = __ldg(v4 + 1);
            const float4 c = __ldg(v4 + 2);
            p[0]=a.x;  p[1]=a.y;  p[2]=a.z;  p[3]=a.w;
            p[4]=bq.x; p[5]=bq.y; p[6]=bq.z; p[7]=bq.w;
            p[8]=c.x;  p[9]=c.y;  p[10]=c.z; p[11]=c.w;
        }
        float bx[10];
        #pragma unroll
        for (int j = 0; j < 10; j++) bx[j] = (off != 0) ? p[j + 2] : p[j];

        // off=0: positions 10,11 are class logits 10,11 (else they're box floats)
        const float e10 = __expf(p[10]);
        const float e11 = __expf(p[11]);
        float s0 = mns * (e10 + e11),          s1 = 0.f, s2 = 0.f, s3 = 0.f;
        float q0 = mns * (e10*e10 + e11*e11),  q1 = 0.f, q2 = 0.f, q3 = 0.f;

        // ---- body: positions 12..91 (vec 3..22) in 4 chunks of 5 vec4 ----
        #pragma unroll
        for (int ch = 0; ch < 4; ch++) {
            float4 u0 = __ldg(v4 + 3 + ch*5 + 0);
            float4 u1 = __ldg(v4 + 3 + ch*5 + 1);
            float4 u2 = __ldg(v4 + 3 + ch*5 + 2);
            float4 u3 = __ldg(v4 + 3 + ch*5 + 3);
            float4 u4 = __ldg(v4 + 3 + ch*5 + 4);
            float q[20] = {u0.x,u0.y,u0.z,u0.w, u1.x,u1.y,u1.z,u1.w,
                           u2.x,u2.y,u2.z,u2.w, u3.x,u3.y,u3.z,u3.w,
                           u4.x,u4.y,u4.z,u4.w};
            #pragma unroll
            for (int i = 0; i < 20; i++) {
                float e = __expf(q[i]);
                // last chunk positions 90,91 are class logits only when off=2
                if (ch == 3 && i >= 18) e *= msh;
                if      ((i & 3) == 0) { s0 += e; q0 += e*e; }
                else if ((i & 3) == 1) { s1 += e; q1 += e*e; }
                else if ((i & 3) == 2) { s2 += e; q2 += e*e; }
                else                   { s3 += e; q3 += e*e; }
            }
        }
        const float s  = (s0 + s1) + (s2 + s3);
        const float sq = (q0 + q1) + (q2 + q3);
        const float el = __expf(cl);
        const float inv = 1.0f / s;
        const float cls_term = sq * inv * inv - 2.0f * el * inv + 1.0f;

        // ---- IoU over both candidate boxes ----
        const float area_g = (x2 - x1) * (y2 - y1);
        float iou[2], sxk[2], syk[2], twk[2], thk[2], tok[2];
        #pragma unroll
        for (int k = 0; k < 2; k++) {
            const float tx = bx[k*5+0], ty = bx[k*5+1];
            const float tw = bx[k*5+2], th = bx[k*5+3];
            const float sx = sigmoidf_(tx);
            const float sy = sigmoidf_(ty);
            const float pw = tw * tw, ph = th * th;
            const float px = (sx + (float)gi) * (1.0f / S_);
            const float py = (sy + (float)gj) * (1.0f / S_);
            const float px1 = px - 0.5f * pw, px2v = px + 0.5f * pw;
            const float py1 = py - 0.5f * ph, py2v = py + 0.5f * ph;
            const float iw = fmaxf(0.f, fminf(px2v, x2) - fmaxf(px1, x1));
            const float ih = fmaxf(0.f, fminf(py2v, y2) - fmaxf(py1, y1));
            const float inter = iw * ih;
            iou[k] = inter / (pw * ph + area_g - inter + 1e-6f);
            sxk[k] = sx; syk[k] = sy; twk[k] = tw; thk[k] = th; tok[k] = bx[k*5+4];
        }
        const int   best = (iou[1] > iou[0]) ? 1 : 0;
        const float iou_best = fmaxf(iou[0], iou[1]);

        const float so  = sigmoidf_(tok[best]);
        const float tgx = cx * (float)S_ - (float)gi;
        const float tgy = cy * (float)S_ - (float)gj;
        const float tgw = sqrtf(w), tgh = sqrtf(h);
        const float dx = sxk[best] - tgx, dy = syk[best] - tgy;
        const float dw = twk[best] - tgw, dh = thk[best] - tgh;
        const float dob = so - iou_best;

        coord   = mval * (dx*dx + dy*dy + dw*dw + dh*dh);
        obj     = mval * dob * dob;
        posconf = mval * so * so;
        npos    = mval;
        clsl    = mval * cls_term;
    }

    // ================= Phase 2: conf over ALL cells =================
    for (int c = t; c < NCELLS; c += NBLK * NTHR) {
        const float* base = preds + (size_t)c * CELLF;
        const float so0 = sigmoidf_(__ldg(base + 4));
        const float so1 = sigmoidf_(__ldg(base + 9));
        noobj += so0 * so0 + so1 * so1;
    }

    // ================= Block reduction -> g_part =================
    float vals[6] = {coord, obj, posconf, clsl, npos, noobj};
    #pragma unroll
    for (int j = 0; j < 6; j++) {
        #pragma unroll
        for (int o = 16; o; o >>= 1)
            vals[j] += __shfl_xor_sync(FULL, vals[j], o);
    }
    __shared__ double sh[NWARP][6];
    if (lane == 0) {
        #pragma unroll
        for (int j = 0; j < 6; j++) sh[wid][j] = (double)vals[j];
    }
    __syncthreads();
    if (tid < 6) {
        double acc = 0.0;
        #pragma unroll
        for (int wI = 0; wI < NWARP; wI++) acc += sh[wI][tid];
        g_part[blockIdx.x][tid] = acc;
    }

    // ================= Grid-wide finalize: last block reduces =================
    __shared__ bool is_last;
    __threadfence();
    if (tid == 0) {
        const unsigned prev = atomicAdd(&g_count, 1u);
        is_last = (prev == (unsigned)(NBLK - 1));
        if (is_last) g_count = 0u;          // reset for the next graph replay
    }
    __syncthreads();
    if (!is_last) return;

    double a[6] = {0, 0, 0, 0, 0, 0};
    for (int bb = tid; bb < NBLK; bb += NTHR) {
        #pragma unroll
        for (int j = 0; j < 6; j++) a[j] += __ldcg(&g_part[bb][j]);
    }
    #pragma unroll
    for (int j = 0; j < 6; j++) {
        #pragma unroll
        for (int o = 16; o; o >>= 1)
            a[j] += __shfl_xor_sync(FULL, a[j], o);
    }
    __shared__ double shf[NWARP][6];
    if (lane == 0) {
        #pragma unroll
        for (int j = 0; j < 6; j++) shf[wid][j] = a[j];
    }
    __syncthreads();
    if (tid == 0) {
        double tt[6];
        #pragma unroll
        for (int j = 0; j < 6; j++) {
            tt[j] = 0.0;
            for (int wI = 0; wI < NWARP; wI++) tt[j] += shf[wI][j];
        }
        const double nposd = fmax(tt[4], 1.0);
        const double nneg  = fmax((double)NBOX - tt[4], 1.0);
        const double ncell = fmax(tt[4], 1.0);   // GT cells are distinct per batch item
        const double loss = 5.0 * tt[0] / nposd          // LC * coord
                          + tt[1] / nposd                // obj
                          + 0.5 * (tt[5] - tt[2]) / nneg // LN * noobj (all - positive)
                          + tt[3] / ncell;               // cls
        *out = (float)loss;
    }
}

extern "C" void kernel_launch(void* const* d_in, const int* in_sizes, int n_in,
                              void* d_out, int out_size)
{
    const float*         preds     = (const float*)d_in[0];
    const float*         gt_boxes  = (const float*)d_in[1];
    const int*           gt_labels = (const int*)d_in[2];
    const unsigned char* gt_valid  = (const unsigned char*)d_in[3];
    float* out = (float*)d_out;

    yolo_loss_fused<<<NBLK, NTHR>>>(preds, gt_boxes, gt_labels, gt_valid, out);
}

// round 4
// speedup vs baseline: 2.6990x; 1.2066x over previous
#include <cuda_runtime.h>
#include <math.h>
#include <float.h>

// Problem constants (fixed by the dataset)
#define S_   7
#define B_   2
#define C_   80
#define NGT  32
#define BT_  8192
#define CELLF 90                    // B*5 + C
#define NCELLS (BT_ * S_ * S_)      // 401408
#define NBOX   (NCELLS * B_)        // 802816
#define NGTS   (BT_ * NGT)          // 262144

#define NTHR 256
#define NBLK 512                    // single wave; 2 GTs per thread
#define NTOT (NBLK * NTHR)          // 131072 threads
#define GPT  (NGTS / NTOT)          // 2 GTs per thread
#define NWARP (NTHR / 32)

// Per-block partial sums: [coord, obj, posconf_sq, cls, npos, noobj_all]
__device__ double g_part[NBLK][6];
__device__ unsigned int g_count = 0;

__device__ __forceinline__ float sigmoidf_(float x) {
    return 1.0f / (1.0f + __expf(-x));
}

__global__ void __launch_bounds__(NTHR, 4)
yolo_loss_fused(const float* __restrict__ preds,
                const float* __restrict__ gt_boxes,
                const int* __restrict__ gt_labels,
                const unsigned char* __restrict__ gt_valid,
                float* __restrict__ out)
{
    const int tid  = threadIdx.x;
    const int lane = tid & 31;
    const int wid  = tid >> 5;
    const int t0   = blockIdx.x * NTHR + tid;
    const unsigned FULL = 0xffffffffu;

    float coord = 0.f, obj = 0.f, posconf = 0.f, clsl = 0.f, npos = 0.f, noobj = 0.f;

    // ================= Phase 1: 2 GTs per thread, fully unrolled =================
    #pragma unroll
    for (int g = 0; g < GPT; g++) {
        const int t = t0 + g * NTOT;

        const float mval = (__ldg(gt_valid + t) != 0) ? 1.0f : 0.0f;
        const float4 gb  = __ldg((const float4*)gt_boxes + t);
        const int   label = __ldg(gt_labels + t);

        const float x1 = gb.x, y1 = gb.y, x2 = gb.z, y2 = gb.w;
        const float cx = (x1 + x2) * 0.5f;
        const float cy = (y1 + y2) * 0.5f;
        const float w  = fmaxf(x2 - x1, 1e-6f);
        const float h  = fmaxf(y2 - y1, 1e-6f);
        const int gi = min(max((int)floorf(cx * (float)S_), 0), S_ - 1);
        const int gj = min(max((int)floorf(cy * (float)S_), 0), S_ - 1);

        const int  b       = t >> 5;                       // t / NGT
        const int  cellIdx = b * (S_ * S_) + gj * S_ + gi;
        const float* cell  = preds + (size_t)cellIdx * CELLF;

        // label-logit gather (independent scalar load, overlaps everything)
        const float cl = __ldg(cell + 10 + label);

        // 16B-aligned vec4 view: off = 0 (even cell) or 2 floats (odd cell)
        const int   off  = (cellIdx & 1) << 1;             // 0 or 2
        const float msh  = (float)(off >> 1);              // 1.0 if shifted
        const float mns  = 1.0f - msh;                     // 1.0 if not shifted
        const float4* v4 = (const float4*)(cell - off);

        // ---- head: loaded positions 0..11 ----
        float p[12];
        {
            const float4 a  = __ldg(v4 + 0);
            const float4 bq = __ldg(v4 + 1);
            const float4 c  = __ldg(v4 + 2);
            p[0]=a.x;  p[1]=a.y;  p[2]=a.z;  p[3]=a.w;
            p[4]=bq.x; p[5]=bq.y; p[6]=bq.z; p[7]=bq.w;
            p[8]=c.x;  p[9]=c.y;  p[10]=c.z; p[11]=c.w;
        }
        float bx[10];
        #pragma unroll
        for (int j = 0; j < 10; j++) bx[j] = (off != 0) ? p[j + 2] : p[j];

        // off=0: positions 10,11 are class logits 10,11 (else box floats)
        const float e10 = __expf(p[10]);
        const float e11 = __expf(p[11]);
        float s0 = mns * (e10 + e11),          s1 = 0.f, s2 = 0.f, s3 = 0.f;
        float q0 = mns * (e10*e10 + e11*e11),  q1 = 0.f, q2 = 0.f, q3 = 0.f;

        // ---- body: positions 12..91 (vec 3..22) in 4 chunks of 5 vec4 ----
        #pragma unroll
        for (int ch = 0; ch < 4; ch++) {
            float4 u0 = __ldg(v4 + 3 + ch*5 + 0);
            float4 u1 = __ldg(v4 + 3 + ch*5 + 1);
            float4 u2 = __ldg(v4 + 3 + ch*5 + 2);
            float4 u3 = __ldg(v4 + 3 + ch*5 + 3);
            float4 u4 = __ldg(v4 + 3 + ch*5 + 4);
            float q[20] = {u0.x,u0.y,u0.z,u0.w, u1.x,u1.y,u1.z,u1.w,
                           u2.x,u2.y,u2.z,u2.w, u3.x,u3.y,u3.z,u3.w,
                           u4.x,u4.y,u4.z,u4.w};
            #pragma unroll
            for (int i = 0; i < 20; i++) {
                float e = __expf(q[i]);
                if (ch == 3 && i >= 18) e *= msh;   // 90,91 valid only when off=2
                if      ((i & 3) == 0) { s0 += e; q0 += e*e; }
                else if ((i & 3) == 1) { s1 += e; q1 += e*e; }
                else if ((i & 3) == 2) { s2 += e; q2 += e*e; }
                else                   { s3 += e; q3 += e*e; }
            }
        }
        const float s  = (s0 + s1) + (s2 + s3);
        const float sq = (q0 + q1) + (q2 + q3);
        const float el = __expf(cl);
        const float inv = 1.0f / s;
        const float cls_term = sq * inv * inv - 2.0f * el * inv + 1.0f;

        // ---- IoU over both candidate boxes ----
        const float area_g = (x2 - x1) * (y2 - y1);
        float iou[2], sxk[2], syk[2], twk[2], thk[2], tok[2];
        #pragma unroll
        for (int k = 0; k < 2; k++) {
            const float tx = bx[k*5+0], ty = bx[k*5+1];
            const float tw = bx[k*5+2], th = bx[k*5+3];
            const float sx = sigmoidf_(tx);
            const float sy = sigmoidf_(ty);
            const float pw = tw * tw, ph = th * th;
            const float px = (sx + (float)gi) * (1.0f / S_);
            const float py = (sy + (float)gj) * (1.0f / S_);
            const float px1 = px - 0.5f * pw, px2v = px + 0.5f * pw;
            const float py1 = py - 0.5f * ph, py2v = py + 0.5f * ph;
            const float iw = fmaxf(0.f, fminf(px2v, x2) - fmaxf(px1, x1));
            const float ih = fmaxf(0.f, fminf(py2v, y2) - fmaxf(py1, y1));
            const float inter = iw * ih;
            iou[k] = inter / (pw * ph + area_g - inter + 1e-6f);
            sxk[k] = sx; syk[k] = sy; twk[k] = tw; thk[k] = th; tok[k] = bx[k*5+4];
        }
        const int   best = (iou[1] > iou[0]) ? 1 : 0;
        const float iou_best = fmaxf(iou[0], iou[1]);

        const float so  = sigmoidf_(tok[best]);
        const float tgx = cx * (float)S_ - (float)gi;
        const float tgy = cy * (float)S_ - (float)gj;
        const float tgw = sqrtf(w), tgh = sqrtf(h);
        const float dx = sxk[best] - tgx, dy = syk[best] - tgy;
        const float dw = twk[best] - tgw, dh = thk[best] - tgh;
        const float dob = so - iou_best;

        coord   += mval * (dx*dx + dy*dy + dw*dw + dh*dh);
        obj     += mval * dob * dob;
        posconf += mval * so * so;
        npos    += mval;
        clsl    += mval * cls_term;
    }

    // ================= Phase 2: conf over ALL cells =================
    for (int c = t0; c < NCELLS; c += NTOT) {
        const float* base = preds + (size_t)c * CELLF;
        const float so0 = sigmoidf_(__ldg(base + 4));
        const float so1 = sigmoidf_(__ldg(base + 9));
        noobj += so0 * so0 + so1 * so1;
    }

    // ================= Block reduction -> g_part =================
    float vals[6] = {coord, obj, posconf, clsl, npos, noobj};
    #pragma unroll
    for (int j = 0; j < 6; j++) {
        #pragma unroll
        for (int o = 16; o; o >>= 1)
            vals[j] += __shfl_xor_sync(FULL, vals[j], o);
    }
    __shared__ double sh[NWARP][6];
    if (lane == 0) {
        #pragma unroll
        for (int j = 0; j < 6; j++) sh[wid][j] = (double)vals[j];
    }
    __syncthreads();
    if (tid < 6) {
        double acc = 0.0;
        #pragma unroll
        for (int wI = 0; wI < NWARP; wI++) acc += sh[wI][tid];
        g_part[blockIdx.x][tid] = acc;
    }

    // ================= Grid-wide finalize: last block reduces =================
    __shared__ bool is_last;
    __threadfence();
    if (tid == 0) {
        const unsigned prev = atomicAdd(&g_count, 1u);
        is_last = (prev == (unsigned)(NBLK - 1));
        if (is_last) g_count = 0u;          // reset for the next graph replay
    }
    __syncthreads();
    if (!is_last) return;

    double a[6] = {0, 0, 0, 0, 0, 0};
    for (int bb = tid; bb < NBLK; bb += NTHR) {
        #pragma unroll
        for (int j = 0; j < 6; j++) a[j] += __ldcg(&g_part[bb][j]);
    }
    #pragma unroll
    for (int j = 0; j < 6; j++) {
        #pragma unroll
        for (int o = 16; o; o >>= 1)
            a[j] += __shfl_xor_sync(FULL, a[j], o);
    }
    __shared__ double shf[NWARP][6];
    if (lane == 0) {
        #pragma unroll
        for (int j = 0; j < 6; j++) shf[wid][j] = a[j];
    }
    __syncthreads();
    if (tid == 0) {
        double tt[6];
        #pragma unroll
        for (int j = 0; j < 6; j++) {
            tt[j] = 0.0;
            for (int wI = 0; wI < NWARP; wI++) tt[j] += shf[wI][j];
        }
        const double nposd = fmax(tt[4], 1.0);
        const double nneg  = fmax((double)NBOX - tt[4], 1.0);
        const double ncell = fmax(tt[4], 1.0);   // GT cells are distinct per batch item
        const double loss = 5.0 * tt[0] / nposd          // LC * coord
                          + tt[1] / nposd                // obj
                          + 0.5 * (tt[5] - tt[2]) / nneg // LN * noobj (all - positive)
                          + tt[3] / ncell;               // cls
        *out = (float)loss;
    }
}

extern "C" void kernel_launch(void* const* d_in, const int* in_sizes, int n_in,
                              void* d_out, int out_size)
{
    const float*         preds     = (const float*)d_in[0];
    const float*         gt_boxes  = (const float*)d_in[1];
    const int*           gt_labels = (const int*)d_in[2];
    const unsigned char* gt_valid  = (const unsigned char*)d_in[3];
    float* out = (float*)d_out;

    yolo_loss_fused<<<NBLK, NTHR>>>(preds, gt_boxes, gt_labels, gt_valid, out);
}